// round 1
// baseline (speedup 1.0000x reference)
#include <cuda_runtime.h>

#define NPTS    262144
#define HIDDEN  20
#define N_MID   8

// pde constants
#define CB      0.5f                 // B
#define CC      0.5f                 // C
#define CSIGMA  1.0f
#define CBF     0.5f                 // B_F
#define CCF     0.9f                 // C_F

// Accurate tanh via MUFU.EX2 (__expf): rel err ~1e-7, robust under --use_fast_math.
__device__ __forceinline__ float tanh_acc(float z) {
    float az = fabsf(z);
    float e  = __expf(-2.0f * az);          // in (0,1]
    float r  = (1.0f - e) / (1.0f + e);     // denom in [1,2] -> safe
    return copysignf(r, z);
}

__global__ __launch_bounds__(256, 1)
void pde_mlp_kernel(const float* __restrict__ x,
                    const float* __restrict__ W_in,
                    const float* __restrict__ b_in,
                    const float* __restrict__ W_mid,
                    const float* __restrict__ b_mid,
                    const float* __restrict__ W_out,
                    const float* __restrict__ b_out,
                    float* __restrict__ out,
                    int n)
{
    __shared__ float sWin[HIDDEN * 2];
    __shared__ float sbin[HIDDEN];
    __shared__ float sWmid[N_MID * HIDDEN * HIDDEN];
    __shared__ float sbmid[N_MID * HIDDEN];
    __shared__ float sWout[HIDDEN];
    __shared__ float sbout;

    const int tid = threadIdx.x;
    for (int i = tid; i < HIDDEN * 2; i += blockDim.x)            sWin[i]  = W_in[i];
    for (int i = tid; i < HIDDEN; i += blockDim.x)                sbin[i]  = b_in[i];
    for (int i = tid; i < N_MID * HIDDEN * HIDDEN; i += blockDim.x) sWmid[i] = W_mid[i];
    for (int i = tid; i < N_MID * HIDDEN; i += blockDim.x)        sbmid[i] = b_mid[i];
    for (int i = tid; i < HIDDEN; i += blockDim.x)                sWout[i] = W_out[i];
    if (tid == 0) sbout = b_out[0];
    __syncthreads();

    const int gid = blockIdx.x * blockDim.x + tid;
    if (gid >= n) return;

    const float2 xi = reinterpret_cast<const float2*>(x)[gid];
    const float t  = xi.x;
    const float xs = xi.y;

    // Forward-mode state: value h, tangents u=dh/dt, v=dh/dx, w=d2h/dx2
    float h[HIDDEN], u[HIDDEN], v[HIDDEN], w[HIDDEN];

    // ---- input layer ----
    #pragma unroll
    for (int j = 0; j < HIDDEN; j++) {
        const float w0 = sWin[2 * j];       // d z / d t
        const float w1 = sWin[2 * j + 1];   // d z / d x
        const float z  = fmaf(w0, t, fmaf(w1, xs, sbin[j]));
        const float a  = tanh_acc(z);
        const float d  = 1.0f - a * a;
        h[j] = a;
        u[j] = d * w0;
        v[j] = d * w1;
        w[j] = -2.0f * a * d * w1 * w1;     // z_vv = 0 at input layer
    }

    // ---- mid layers (rolled loop; inner fully unrolled) ----
    for (int layer = 0; layer < N_MID; layer++) {
        const float* __restrict__ Wl = &sWmid[layer * HIDDEN * HIDDEN];
        const float* __restrict__ bl = &sbmid[layer * HIDDEN];

        float nh[HIDDEN], nu[HIDDEN], nv[HIDDEN], nw[HIDDEN];
        #pragma unroll
        for (int j = 0; j < HIDDEN; j++) {
            float z  = bl[j];
            float zu = 0.0f, zv = 0.0f, zw = 0.0f;
            #pragma unroll
            for (int k = 0; k < HIDDEN; k++) {
                const float wt = Wl[j * HIDDEN + k];
                z  = fmaf(wt, h[k], z);
                zu = fmaf(wt, u[k], zu);
                zv = fmaf(wt, v[k], zv);
                zw = fmaf(wt, w[k], zw);
            }
            const float a = tanh_acc(z);
            const float d = 1.0f - a * a;
            nh[j] = a;
            nu[j] = d * zu;
            nv[j] = d * zv;
            nw[j] = fmaf(d, zw, -2.0f * a * d * zv * zv);
        }
        #pragma unroll
        for (int j = 0; j < HIDDEN; j++) {
            h[j] = nh[j]; u[j] = nu[j]; v[j] = nv[j]; w[j] = nw[j];
        }
    }

    // ---- output layer (linear) ----
    float f  = sbout;
    float fu = 0.0f, fv = 0.0f, fw = 0.0f;
    #pragma unroll
    for (int k = 0; k < HIDDEN; k++) {
        const float wt = sWout[k];
        f  = fmaf(wt, h[k], f);
        fu = fmaf(wt, u[k], fu);
        fv = fmaf(wt, v[k], fv);
        fw = fmaf(wt, w[k], fw);
    }

    // pde = B_F*x^2 + f_t + 0.5*sigma^2*f_xx + B*x*f_x - C^2/(4*C_F)*f_x^2
    const float pde = CBF * xs * xs
                    + fu
                    + 0.5f * CSIGMA * CSIGMA * fw
                    + CB * xs * fv
                    - (CC * CC / (4.0f * CCF)) * fv * fv;

    out[gid]     = f;
    out[n + gid] = pde;
}

extern "C" void kernel_launch(void* const* d_in, const int* in_sizes, int n_in,
                              void* d_out, int out_size)
{
    const float* x     = (const float*)d_in[0];
    const float* W_in  = (const float*)d_in[1];
    const float* b_in  = (const float*)d_in[2];
    const float* W_mid = (const float*)d_in[3];
    const float* b_mid = (const float*)d_in[4];
    const float* W_out = (const float*)d_in[5];
    const float* b_out = (const float*)d_in[6];
    float* out = (float*)d_out;

    const int n = in_sizes[0] / 2;   // x is (N, 2)
    const int threads = 256;
    const int blocks  = (n + threads - 1) / threads;
    pde_mlp_kernel<<<blocks, threads>>>(x, W_in, b_in, W_mid, b_mid,
                                        W_out, b_out, out, n);
}

// round 2
// speedup vs baseline: 1.3319x; 1.3319x over previous
#include <cuda_runtime.h>

#define HIDDEN  20
#define N_MID   8

// pde constants
#define CB      0.5f                 // B
#define CC      0.5f                 // C
#define CSIGMA  1.0f
#define CBF     0.5f                 // B_F
#define CCF     0.9f                 // C_F

// ---------------- packed f32x2 helpers (Blackwell) ----------------
__device__ __forceinline__ unsigned long long pack2(float lo, float hi) {
    unsigned long long r;
    asm("mov.b64 %0, {%1, %2};" : "=l"(r) : "f"(lo), "f"(hi));
    return r;
}
__device__ __forceinline__ void unpack2(unsigned long long p, float& lo, float& hi) {
    asm("mov.b64 {%0, %1}, %2;" : "=f"(lo), "=f"(hi) : "l"(p));
}
__device__ __forceinline__ unsigned long long fma2(unsigned long long a,
                                                   unsigned long long b,
                                                   unsigned long long c) {
    unsigned long long r;
    asm("fma.rn.f32x2 %0, %1, %2, %3;" : "=l"(r) : "l"(a), "l"(b), "l"(c));
    return r;
}

// Accurate-enough tanh: EX2-based exp + approx reciprocal (rel err ~2^-22).
__device__ __forceinline__ float tanh_acc(float z) {
    float az = fabsf(z);
    float e  = __expf(-2.0f * az);                 // MUFU.EX2 path, (0,1]
    float r  = __fdividef(1.0f - e, 1.0f + e);     // MUFU.RCP + mul
    return copysignf(r, z);
}

__global__ __launch_bounds__(256, 1)
void pde_mlp_kernel(const float* __restrict__ x,
                    const float* __restrict__ W_in,
                    const float* __restrict__ b_in,
                    const float* __restrict__ W_mid,
                    const float* __restrict__ b_mid,
                    const float* __restrict__ W_out,
                    const float* __restrict__ b_out,
                    float* __restrict__ out,
                    int n)
{
    // duplicated (w,w) packed weights so inner loop is LDS.64 + 2x FFMA2
    __shared__ unsigned long long sW2[N_MID * HIDDEN * HIDDEN];   // 25.6 KB
    __shared__ unsigned long long sB2[N_MID * HIDDEN];            // (b, 0) pairs
    __shared__ unsigned long long sWout2[HIDDEN];
    __shared__ float sWin[HIDDEN * 2];
    __shared__ float sbin[HIDDEN];
    __shared__ float sbout;

    const int tid = threadIdx.x;
    for (int i = tid; i < N_MID * HIDDEN * HIDDEN; i += blockDim.x) {
        const float wv = W_mid[i];
        sW2[i] = pack2(wv, wv);
    }
    for (int i = tid; i < N_MID * HIDDEN; i += blockDim.x)
        sB2[i] = pack2(b_mid[i], 0.0f);
    for (int i = tid; i < HIDDEN; i += blockDim.x) {
        const float wv = W_out[i];
        sWout2[i] = pack2(wv, wv);
        sbin[i]   = b_in[i];
    }
    for (int i = tid; i < HIDDEN * 2; i += blockDim.x) sWin[i] = W_in[i];
    if (tid == 0) sbout = b_out[0];
    __syncthreads();

    const int gid = blockIdx.x * blockDim.x + tid;
    if (gid >= n) return;

    const float2 xi = reinterpret_cast<const float2*>(x)[gid];
    const float t  = xi.x;
    const float xs = xi.y;

    // Packed forward-mode state: hu = (h, dh/dt), vw = (dh/dx, d2h/dx2)
    unsigned long long hu[HIDDEN], vw[HIDDEN];

    // ---- input layer (scalar, tiny) ----
    #pragma unroll
    for (int j = 0; j < HIDDEN; j++) {
        const float w0 = sWin[2 * j];       // dz/dt
        const float w1 = sWin[2 * j + 1];   // dz/dx
        const float z  = fmaf(w0, t, fmaf(w1, xs, sbin[j]));
        const float a  = tanh_acc(z);
        const float d  = 1.0f - a * a;
        hu[j] = pack2(a, d * w0);
        vw[j] = pack2(d * w1, -2.0f * a * d * w1 * w1);
    }

    // ---- mid layers ----
    for (int layer = 0; layer < N_MID; layer++) {
        const unsigned long long* __restrict__ Wl = &sW2[layer * HIDDEN * HIDDEN];
        const unsigned long long* __restrict__ bl = &sB2[layer * HIDDEN];

        unsigned long long nhu[HIDDEN], nvw[HIDDEN];
        #pragma unroll
        for (int j = 0; j < HIDDEN; j++) {
            unsigned long long zhu = bl[j];               // (b, 0)
            unsigned long long zvw = pack2(0.0f, 0.0f);
            #pragma unroll
            for (int k = 0; k < HIDDEN; k++) {
                const unsigned long long ww = Wl[j * HIDDEN + k];
                zhu = fma2(ww, hu[k], zhu);
                zvw = fma2(ww, vw[k], zvw);
            }
            float z, zu, zv, zw;
            unpack2(zhu, z, zu);
            unpack2(zvw, zv, zw);
            const float a = tanh_acc(z);
            const float d = 1.0f - a * a;
            nhu[j] = pack2(a, d * zu);
            nvw[j] = pack2(d * zv, fmaf(d, zw, -2.0f * a * d * zv * zv));
        }
        #pragma unroll
        for (int j = 0; j < HIDDEN; j++) { hu[j] = nhu[j]; vw[j] = nvw[j]; }
    }

    // ---- output layer (linear) ----
    unsigned long long fhu = pack2(sbout, 0.0f);
    unsigned long long fvw = pack2(0.0f, 0.0f);
    #pragma unroll
    for (int k = 0; k < HIDDEN; k++) {
        const unsigned long long ww = sWout2[k];
        fhu = fma2(ww, hu[k], fhu);
        fvw = fma2(ww, vw[k], fvw);
    }
    float f, fu, fv, fw;
    unpack2(fhu, f, fu);
    unpack2(fvw, fv, fw);

    const float pde = CBF * xs * xs
                    + fu
                    + 0.5f * CSIGMA * CSIGMA * fw
                    + CB * xs * fv
                    - (CC * CC / (4.0f * CCF)) * fv * fv;

    out[gid]     = f;
    out[n + gid] = pde;
}

extern "C" void kernel_launch(void* const* d_in, const int* in_sizes, int n_in,
                              void* d_out, int out_size)
{
    const float* x     = (const float*)d_in[0];
    const float* W_in  = (const float*)d_in[1];
    const float* b_in  = (const float*)d_in[2];
    const float* W_mid = (const float*)d_in[3];
    const float* b_mid = (const float*)d_in[4];
    const float* W_out = (const float*)d_in[5];
    const float* b_out = (const float*)d_in[6];
    float* out = (float*)d_out;

    const int n = in_sizes[0] / 2;   // x is (N, 2)
    const int threads = 256;
    const int blocks  = (n + threads - 1) / threads;
    pde_mlp_kernel<<<blocks, threads>>>(x, W_in, b_in, W_mid, b_mid,
                                        W_out, b_out, out, n);
}